// round 3
// baseline (speedup 1.0000x reference)
#include <cuda_runtime.h>
#include <stdint.h>

// Problem constants (fixed by the reference).
#define Bn 32
#define Tn 4096
#define Dn 512
#define Un 512
#define TSEG 8   // t-segments for the context partial pass

// Scratch (no device allocation allowed -> __device__ globals).
__device__ float g_qb[Bn * Un];              // q_proj + b1 + b2, per batch
__device__ float g_scores[Bn * Tn];          // scores, then attn in-place
__device__ float g_ctxpart[Bn * TSEG * Dn];  // partial context sums

__device__ __forceinline__ uint32_t f2tf(float x) {
    uint32_t u;
    asm("cvt.rna.tf32.f32 %0, %1;" : "=r"(u) : "f"(x));
    return u;
}

__device__ __forceinline__ float fast_tanh(float x) {
    float y;
    asm("tanh.approx.f32 %0, %1;" : "=f"(y) : "f"(x));
    return y;
}

// ---------------------------------------------------------------------------
// Kernel 1: g_qb[b][u] = query[b]@W1[:,u] + b1[u] + b2[u]   (fp32, tiny)
// ---------------------------------------------------------------------------
__global__ void qproj_kernel(const float* __restrict__ query,
                             const float* __restrict__ W1,
                             const float* __restrict__ b1,
                             const float* __restrict__ b2) {
    __shared__ float qs[Dn];
    const int b = blockIdx.x;
    const int u = threadIdx.x;  // 512 threads
    qs[u] = query[b * Dn + u];
    __syncthreads();
    float acc = b1[u] + b2[u];
#pragma unroll 8
    for (int d = 0; d < Dn; ++d)
        acc = fmaf(qs[d], W1[d * Un + u], acc);
    g_qb[b * Un + u] = acc;
}

// ---------------------------------------------------------------------------
// Kernel 2: fused  scores[b,t] = tanh(values[b,t]@W2 + qb[b]) @ V + bv
// tf32 mma.sync m16n8k8; 128 t-rows per block; U chunked 4x128;
// K tiled at 16 with 2-stage smem double buffering (LDG || MMA overlap).
// 8 warps as 4 warp-rows x 2 warp-cols; each warp owns 32 rows x 64 cols
// (B fragments amortized over 2 m-tiles -> fewer LDS per HMMA).
// ---------------------------------------------------------------------------
__global__ __launch_bounds__(256) void scores_kernel(
        const float* __restrict__ values,
        const float* __restrict__ W2,
        const float* __restrict__ Vv,
        const float* __restrict__ bv) {
    constexpr int BT = 128;          // t-rows per block
    constexpr int KT = 16;           // K tile
    constexpr int NK = Dn / KT;      // 32

    // A pad 20: bank(row, k) = (20*row + k) % 32 permutes over lanes ->
    //           conflict-free fragment loads. (row offsets 8/16 are 32-bank
    //           multiples -> same property for every fragment.)
    // B pad 132: fragment loads <=2-way; 132%4==0 so &Bs[r][q*4] is 16B
    //           aligned -> STS.128 stores, conflict-free per 8-lane phase.
    __shared__ float As[2][BT][20];
    __shared__ float Bs[2][KT][132];
    __shared__ float qbs[Un];
    __shared__ float Vs[Un];
    __shared__ float sred[4][2][4][8];  // [warp-row][warp-col][row-sub][g]

    const int b   = blockIdx.y;
    const int t0  = blockIdx.x * BT;
    const int tid = threadIdx.x;
    const int warp = tid >> 5, lane = tid & 31;
    const int wr = warp >> 1, wc = warp & 1;   // warp-row / warp-col
    const int g = lane >> 2, tg = lane & 3;    // groupID / threadID_in_group

    for (int i = tid; i < Un; i += 256) {
        qbs[i] = g_qb[b * Un + i];
        Vs[i]  = Vv[i];
    }

    const float* vbase = values + (size_t)b * Tn * Dn;

    // 4 score partials: rows wr*32 + mt*16 + g + r8*8, j = mt*2 + r8
    float sc[4] = {0.f, 0.f, 0.f, 0.f};

    for (int uc = 0; uc < 4; ++uc) {
        float acc[2][8][4];
#pragma unroll
        for (int mt = 0; mt < 2; ++mt)
#pragma unroll
            for (int nt = 0; nt < 8; ++nt)
#pragma unroll
                for (int i = 0; i < 4; ++i) acc[mt][nt][i] = 0.f;

        // ---- prologue: load K-tile 0 into buffer 0 ----
#pragma unroll
        for (int it = 0; it < 2; ++it) {
            int idx = it * 256 + tid;
            {   // A: 128 rows x 16 cols
                int r = idx >> 2, q = idx & 3;
                float4 v = *(const float4*)(vbase + (size_t)(t0 + r) * Dn + q * 4);
                As[0][r][q * 4 + 0] = __uint_as_float(f2tf(v.x));
                As[0][r][q * 4 + 1] = __uint_as_float(f2tf(v.y));
                As[0][r][q * 4 + 2] = __uint_as_float(f2tf(v.z));
                As[0][r][q * 4 + 3] = __uint_as_float(f2tf(v.w));
            }
            {   // B: 16 rows x 128 cols
                int r = idx >> 5, q = idx & 31;
                float4 v = *(const float4*)(W2 + (size_t)r * Un + uc * 128 + q * 4);
                float4 w;
                w.x = __uint_as_float(f2tf(v.x));
                w.y = __uint_as_float(f2tf(v.y));
                w.z = __uint_as_float(f2tf(v.z));
                w.w = __uint_as_float(f2tf(v.w));
                *(float4*)&Bs[0][r][q * 4] = w;
            }
        }
        __syncthreads();

        for (int kt = 0; kt < NK; ++kt) {
            const int cur = kt & 1, nxt = cur ^ 1;

            // ---- issue next tile's global loads (overlap with MMA) ----
            float4 la[2], lb[2];
            if (kt + 1 < NK) {
#pragma unroll
                for (int it = 0; it < 2; ++it) {
                    int idx = it * 256 + tid;
                    int ra = idx >> 2, qa = idx & 3;
                    la[it] = *(const float4*)(vbase + (size_t)(t0 + ra) * Dn +
                                              (kt + 1) * KT + qa * 4);
                    int rb = idx >> 5, qb = idx & 31;
                    lb[it] = *(const float4*)(W2 + (size_t)((kt + 1) * KT + rb) * Un +
                                              uc * 128 + qb * 4);
                }
            }

            // ---- MMA on current buffer ----
#pragma unroll
            for (int kk = 0; kk < 2; ++kk) {
                const int kc = kk * 8 + tg;
                uint32_t a[2][4];
#pragma unroll
                for (int mt = 0; mt < 2; ++mt) {
                    const int row = wr * 32 + mt * 16 + g;
                    a[mt][0] = __float_as_uint(As[cur][row][kc]);
                    a[mt][1] = __float_as_uint(As[cur][row + 8][kc]);
                    a[mt][2] = __float_as_uint(As[cur][row][kc + 4]);
                    a[mt][3] = __float_as_uint(As[cur][row + 8][kc + 4]);
                }
#pragma unroll
                for (int nt = 0; nt < 8; ++nt) {
                    const int col = wc * 64 + nt * 8 + g;
                    uint32_t bb0 = __float_as_uint(Bs[cur][kc][col]);
                    uint32_t bb1 = __float_as_uint(Bs[cur][kc + 4][col]);
#pragma unroll
                    for (int mt = 0; mt < 2; ++mt) {
                        asm volatile(
                            "mma.sync.aligned.m16n8k8.row.col.f32.tf32.tf32.f32 "
                            "{%0,%1,%2,%3}, {%4,%5,%6,%7}, {%8,%9}, {%0,%1,%2,%3};\n"
                            : "+f"(acc[mt][nt][0]), "+f"(acc[mt][nt][1]),
                              "+f"(acc[mt][nt][2]), "+f"(acc[mt][nt][3])
                            : "r"(a[mt][0]), "r"(a[mt][1]),
                              "r"(a[mt][2]), "r"(a[mt][3]),
                              "r"(bb0), "r"(bb1));
                    }
                }
            }

            // ---- store next tile (nxt last read at kt-1, fenced by sync) ----
            if (kt + 1 < NK) {
#pragma unroll
                for (int it = 0; it < 2; ++it) {
                    int idx = it * 256 + tid;
                    int ra = idx >> 2, qa = idx & 3;
                    As[nxt][ra][qa * 4 + 0] = __uint_as_float(f2tf(la[it].x));
                    As[nxt][ra][qa * 4 + 1] = __uint_as_float(f2tf(la[it].y));
                    As[nxt][ra][qa * 4 + 2] = __uint_as_float(f2tf(la[it].z));
                    As[nxt][ra][qa * 4 + 3] = __uint_as_float(f2tf(la[it].w));
                    int rb = idx >> 5, qb = idx & 31;
                    float4 w;
                    w.x = __uint_as_float(f2tf(lb[it].x));
                    w.y = __uint_as_float(f2tf(lb[it].y));
                    w.z = __uint_as_float(f2tf(lb[it].z));
                    w.w = __uint_as_float(f2tf(lb[it].w));
                    *(float4*)&Bs[nxt][rb][qb * 4] = w;
                }
            }
            __syncthreads();
        }

        // Epilogue for this u-chunk: tanh(P + qb) * V, reduce over u.
#pragma unroll
        for (int mt = 0; mt < 2; ++mt)
#pragma unroll
            for (int nt = 0; nt < 8; ++nt) {
                int u = uc * 128 + wc * 64 + nt * 8 + tg * 2;
                sc[mt * 2 + 0] += fast_tanh(acc[mt][nt][0] + qbs[u])     * Vs[u];
                sc[mt * 2 + 0] += fast_tanh(acc[mt][nt][1] + qbs[u + 1]) * Vs[u + 1];
                sc[mt * 2 + 1] += fast_tanh(acc[mt][nt][2] + qbs[u])     * Vs[u];
                sc[mt * 2 + 1] += fast_tanh(acc[mt][nt][3] + qbs[u + 1]) * Vs[u + 1];
            }
    }
    // Reduce across the 4 lanes sharing each row (tg = 0..3).
#pragma unroll
    for (int j = 0; j < 4; ++j) {
        sc[j] += __shfl_xor_sync(0xffffffffu, sc[j], 1);
        sc[j] += __shfl_xor_sync(0xffffffffu, sc[j], 2);
    }
    if (tg == 0) {
#pragma unroll
        for (int j = 0; j < 4; ++j) sred[wr][wc][j][g] = sc[j];
    }
    __syncthreads();
    // Combine the two warp-column halves; 128 threads write 128 rows.
    if (tid < 128) {
        const int pr = tid >> 5;        // warp-row 0..3
        const int j  = (tid >> 3) & 3;  // row-sub 0..3
        const int pg = tid & 7;         // g 0..7
        const float s = sred[pr][0][j][pg] + sred[pr][1][j][pg] + bv[0];
        const int r = t0 + pr * 32 + (j >> 1) * 16 + (j & 1) * 8 + pg;
        g_scores[b * Tn + r] = s;
    }
}

// ---------------------------------------------------------------------------
// Kernel 3: softmax over T (one block per batch, in-place on g_scores)
// ---------------------------------------------------------------------------
__global__ void softmax_kernel() {
    __shared__ float red[256];
    const int b = blockIdx.x, tid = threadIdx.x;
    float v[16];
    float mx = -1e30f;
#pragma unroll
    for (int i = 0; i < 16; ++i) {
        v[i] = g_scores[b * Tn + i * 256 + tid];
        mx = fmaxf(mx, v[i]);
    }
    red[tid] = mx;
    __syncthreads();
    for (int s = 128; s > 0; s >>= 1) {
        if (tid < s) red[tid] = fmaxf(red[tid], red[tid + s]);
        __syncthreads();
    }
    mx = red[0];
    __syncthreads();
    float sum = 0.f;
#pragma unroll
    for (int i = 0; i < 16; ++i) {
        v[i] = __expf(v[i] - mx);
        sum += v[i];
    }
    red[tid] = sum;
    __syncthreads();
    for (int s = 128; s > 0; s >>= 1) {
        if (tid < s) red[tid] += red[tid + s];
        __syncthreads();
    }
    const float inv = 1.0f / red[0];
#pragma unroll
    for (int i = 0; i < 16; ++i)
        g_scores[b * Tn + i * 256 + tid] = v[i] * inv;
}

// ---------------------------------------------------------------------------
// Kernel 4: partial context  (b, t-segment, d-chunk) -> g_ctxpart
// HBM-streaming pass over values; 1024 blocks for latency hiding.
// ---------------------------------------------------------------------------
__global__ __launch_bounds__(128) void ctx_partial_kernel(const float* __restrict__ values) {
    const int b  = blockIdx.z;
    const int ts = blockIdx.y;
    const int d  = blockIdx.x * 128 + threadIdx.x;
    const int tlen = Tn / TSEG;  // 512
    const float* vb = values + ((size_t)b * Tn + (size_t)ts * tlen) * Dn + d;
    const float* ab = g_scores + b * Tn + ts * tlen;
    float acc = 0.f;
#pragma unroll 8
    for (int t = 0; t < tlen; ++t)
        acc = fmaf(ab[t], vb[(size_t)t * Dn], acc);
    g_ctxpart[(b * TSEG + ts) * Dn + d] = acc;
}

// ---------------------------------------------------------------------------
// Kernel 5: deterministic reduce of partials -> out[b, d]
// ---------------------------------------------------------------------------
__global__ void ctx_reduce_kernel(float* __restrict__ out) {
    const int i = blockIdx.x * 256 + threadIdx.x;  // 16384 total
    const int b = i >> 9, d = i & 511;
    float s = 0.f;
#pragma unroll
    for (int ts = 0; ts < TSEG; ++ts)
        s += g_ctxpart[(b * TSEG + ts) * Dn + d];
    out[i] = s;
}

// ---------------------------------------------------------------------------
extern "C" void kernel_launch(void* const* d_in, const int* in_sizes, int n_in,
                              void* d_out, int out_size) {
    const float* query  = (const float*)d_in[0];
    const float* values = (const float*)d_in[1];
    const float* W1     = (const float*)d_in[2];
    const float* b1     = (const float*)d_in[3];
    const float* W2     = (const float*)d_in[4];
    const float* b2     = (const float*)d_in[5];
    const float* V      = (const float*)d_in[6];
    const float* bv     = (const float*)d_in[7];
    float* out = (float*)d_out;

    qproj_kernel<<<Bn, Dn>>>(query, W1, b1, b2);
    scores_kernel<<<dim3(Tn / 128, Bn), 256>>>(values, W2, V, bv);
    softmax_kernel<<<Bn, 256>>>();
    ctx_partial_kernel<<<dim3(Dn / 128, TSEG, Bn), 128>>>(values);
    ctx_reduce_kernel<<<(Bn * Dn) / 256, 256>>>(out);
}